// round 12
// baseline (speedup 1.0000x reference)
#include <cuda_runtime.h>
#include <cstdint>

#define NBH 64
#define L   512
#define DD  64
#define SQP 68    // sQ / sV row pad (floats)
#define SKP 260   // sKT / sP row pad (floats)
#define SVP 68

typedef unsigned long long ull;

// Scratch (device globals; no allocation in kernel_launch)
__device__ float g_ksumT[NBH * DD * L];   // [bh][d][j]  (transposed)
__device__ float g_vsum [NBH * L * DD];   // [bh][j][d]  (natural)

__device__ __forceinline__ ull pack2(float x) {
    ull r; unsigned int xi = __float_as_uint(x);
    asm("mov.b64 %0, {%1, %1};" : "=l"(r) : "r"(xi));
    return r;
}
__device__ __forceinline__ void ffma2(ull& c, ull a, ull b) {
    asm("fma.rn.f32x2 %0, %1, %2, %0;" : "+l"(c) : "l"(a), "l"(b));
}
__device__ __forceinline__ float2 unpack2(ull x) {
    float2 f;
    asm("mov.b64 {%0, %1}, %2;" : "=f"(f.x), "=f"(f.y) : "l"(x));
    return f;
}

// ---------------------------------------------------------------------------
// K1: reduce r; ksum TRANSPOSED [bh][d][j] via smem transpose, vsum natural.
// ---------------------------------------------------------------------------
__global__ __launch_bounds__(256)
void reduce_kv_kernel(const float* __restrict__ k, const float* __restrict__ v) {
    __shared__ float sT[DD * 65];
    const int t  = threadIdx.x;
    const int jb = blockIdx.x;
    const int bh = blockIdx.y;

    #pragma unroll
    for (int p = 0; p < 4; ++p) {
        int f4 = p * 256 + t;
        int jl = f4 >> 4, dq = (f4 & 15) << 2;
        size_t base = (((size_t)bh * L + jb * 64 + jl) * 4) * DD + dq;
        float4 a0 = *(const float4*)(k + base);
        float4 a1 = *(const float4*)(k + base + DD);
        float4 a2 = *(const float4*)(k + base + 2 * DD);
        float4 a3 = *(const float4*)(k + base + 3 * DD);
        sT[(dq + 0) * 65 + jl] = (a0.x + a1.x) + (a2.x + a3.x);
        sT[(dq + 1) * 65 + jl] = (a0.y + a1.y) + (a2.y + a3.y);
        sT[(dq + 2) * 65 + jl] = (a0.z + a1.z) + (a2.z + a3.z);
        sT[(dq + 3) * 65 + jl] = (a0.w + a1.w) + (a2.w + a3.w);
        float4 b0 = *(const float4*)(v + base);
        float4 b1 = *(const float4*)(v + base + DD);
        float4 b2 = *(const float4*)(v + base + 2 * DD);
        float4 b3 = *(const float4*)(v + base + 3 * DD);
        float4 vs;
        vs.x = (b0.x + b1.x) + (b2.x + b3.x);
        vs.y = (b0.y + b1.y) + (b2.y + b3.y);
        vs.z = (b0.z + b1.z) + (b2.z + b3.z);
        vs.w = (b0.w + b1.w) + (b2.w + b3.w);
        *(float4*)(g_vsum + ((size_t)bh * L + jb * 64 + jl) * DD + dq) = vs;
    }
    __syncthreads();
    #pragma unroll
    for (int p = 0; p < 4; ++p) {
        int f4 = p * 256 + t;
        int dl = f4 >> 4, jq = (f4 & 15) << 2;
        float4 o;
        o.x = sT[dl * 65 + jq + 0];
        o.y = sT[dl * 65 + jq + 1];
        o.z = sT[dl * 65 + jq + 2];
        o.w = sT[dl * 65 + jq + 3];
        *(float4*)(g_ksumT + ((size_t)bh * DD + dl) * L + jb * 64 + jq) = o;
    }
}

// ---------------------------------------------------------------------------
// K2 (fused): per CTA 64 q rows of one bh.
//   c=0: S chunk -> raw store to attn, online stats
//   c=1: S chunk -> stats finalize -> normalized P to attn + sP(smem)
//   PV chunk1 from sP; chunk0 fixup (L2 re-read, normalize, attn + sP);
//   PV chunk0; write O.
// smem: sQ[64][68] (aliased by sV) | sKT[64][260] (aliased by sP) = 84KB.
// ---------------------------------------------------------------------------
extern __shared__ float smem[];

__global__ __launch_bounds__(256, 2)
void attn_fused(const float* __restrict__ q,
                const float* __restrict__ omega,
                const int*   __restrict__ mask,
                float* __restrict__ attn,
                float* __restrict__ out_o) {
    float* sQ  = smem;              // [64][SQP]
    float* sKT = smem + 64 * SQP;   // [64][SKP]
    float* sV  = sQ;                // alias (sQ dead after QK mainloops)
    float* sP  = sKT;               // alias (sKT dead after c=1 mainloop)

    const int t  = threadIdx.x;
    const int bh = blockIdx.y;
    const int b  = bh >> 3;
    const int qb = blockIdx.x * 64;
    const int w  = t >> 5, l = t & 31;

    // fill sQ (fold 1/8)
    #pragma unroll
    for (int p = 0; p < 4; ++p) {
        int f4 = p * 256 + t;
        int r = f4 >> 4, dq = (f4 & 15) << 2;
        float4 qv = *(const float4*)(q + ((size_t)bh * L + qb + r) * DD + dq);
        qv.x *= 0.125f; qv.y *= 0.125f; qv.z *= 0.125f; qv.w *= 0.125f;
        *(float4*)(sQ + r * SQP + dq) = qv;
    }

    float M[8], Z[8], Zinv[8];
    #pragma unroll
    for (int r = 0; r < 8; ++r) { M[r] = -3.4e38f; Z[r] = 0.f; }

    #pragma unroll
    for (int c = 0; c < 2; ++c) {
        __syncthreads();
        // fill sKT chunk c
        #pragma unroll
        for (int p = 0; p < 16; ++p) {
            int f4 = p * 256 + t;
            int d = f4 >> 6, cq = (f4 & 63) << 2;
            *(float4*)(sKT + d * SKP + cq) =
                *(const float4*)(g_ksumT + ((size_t)bh * DD + d) * L + c * 256 + cq);
        }
        __syncthreads();

        ull acc[8][4];
        #pragma unroll
        for (int r = 0; r < 8; ++r)
            #pragma unroll
            for (int i = 0; i < 4; ++i) acc[r][i] = 0;

        const float* bp = sKT + 4 * l;
        #pragma unroll 2
        for (int d = 0; d < DD; d += 2) {
            float2 a[8];
            #pragma unroll
            for (int r = 0; r < 8; ++r)
                a[r] = *(const float2*)(sQ + (8 * w + r) * SQP + d);
            #pragma unroll
            for (int dd = 0; dd < 2; ++dd) {
                ulonglong2 b0 = *(const ulonglong2*)(bp + (d + dd) * SKP);
                ulonglong2 b1 = *(const ulonglong2*)(bp + (d + dd) * SKP + 128);
                #pragma unroll
                for (int r = 0; r < 8; ++r) {
                    ull ar = pack2(dd ? a[r].y : a[r].x);
                    ffma2(acc[r][0], ar, b0.x);
                    ffma2(acc[r][1], ar, b0.y);
                    ffma2(acc[r][2], ar, b1.x);
                    ffma2(acc[r][3], ar, b1.y);
                }
            }
        }

        if (c == 1) __syncthreads();  // sKT reads done before sP writes below

        #pragma unroll
        for (int r = 0; r < 8; ++r) {
            int gi = qb + 8 * w + r;
            size_t orow = ((size_t)b * L + gi) * L + c * 256;
            float4 o0 = *(const float4*)(omega + orow + 4 * l);
            float4 o1 = *(const float4*)(omega + orow + 128 + 4 * l);
            int4 m0 = *(const int4*)(mask + orow + 4 * l);
            int4 m1 = *(const int4*)(mask + orow + 128 + 4 * l);
            float2 u0 = unpack2(acc[r][0]), u1 = unpack2(acc[r][1]);
            float2 u2 = unpack2(acc[r][2]), u3 = unpack2(acc[r][3]);
            float s0 = m0.x ? -1e9f : u0.x * o0.x;
            float s1 = m0.y ? -1e9f : u0.y * o0.y;
            float s2 = m0.z ? -1e9f : u1.x * o0.z;
            float s3 = m0.w ? -1e9f : u1.y * o0.w;
            float s4 = m1.x ? -1e9f : u2.x * o1.x;
            float s5 = m1.y ? -1e9f : u2.y * o1.y;
            float s6 = m1.z ? -1e9f : u3.x * o1.z;
            float s7 = m1.w ? -1e9f : u3.y * o1.w;

            float cm = fmaxf(fmaxf(fmaxf(s0, s1), fmaxf(s2, s3)),
                             fmaxf(fmaxf(s4, s5), fmaxf(s6, s7)));
            #pragma unroll
            for (int o = 16; o > 0; o >>= 1)
                cm = fmaxf(cm, __shfl_xor_sync(0xffffffffu, cm, o));
            float nM = fmaxf(M[r], cm);
            float cs = __expf(s0 - nM) + __expf(s1 - nM) + __expf(s2 - nM) + __expf(s3 - nM)
                     + __expf(s4 - nM) + __expf(s5 - nM) + __expf(s6 - nM) + __expf(s7 - nM);
            #pragma unroll
            for (int o = 16; o > 0; o >>= 1)
                cs += __shfl_xor_sync(0xffffffffu, cs, o);
            Z[r] = Z[r] * __expf(M[r] - nM) + cs;
            M[r] = nM;

            size_t arow = ((size_t)bh * L + gi) * L + c * 256;
            if (c == 0) {
                // raw store; fixed up after stats are final
                *(float4*)(attn + arow + 4 * l)       = make_float4(s0, s1, s2, s3);
                *(float4*)(attn + arow + 128 + 4 * l) = make_float4(s4, s5, s6, s7);
            } else {
                float iz = 1.0f / Z[r];
                Zinv[r] = iz;
                float p0 = __expf(s0 - M[r]) * iz, p1 = __expf(s1 - M[r]) * iz;
                float p2 = __expf(s2 - M[r]) * iz, p3 = __expf(s3 - M[r]) * iz;
                float p4 = __expf(s4 - M[r]) * iz, p5 = __expf(s5 - M[r]) * iz;
                float p6 = __expf(s6 - M[r]) * iz, p7 = __expf(s7 - M[r]) * iz;
                *(float4*)(attn + arow + 4 * l)       = make_float4(p0, p1, p2, p3);
                *(float4*)(attn + arow + 128 + 4 * l) = make_float4(p4, p5, p6, p7);
                *(float4*)(sP + (8 * w + r) * SKP + 4 * l)       = make_float4(p0, p1, p2, p3);
                *(float4*)(sP + (8 * w + r) * SKP + 128 + 4 * l) = make_float4(p4, p5, p6, p7);
            }
        }
    }

    // ------------------- PV accumulation -------------------
    const float* vbase = g_vsum + (size_t)bh * L * DD;
    ull oacc[8];
    #pragma unroll
    for (int r = 0; r < 8; ++r) oacc[r] = 0;

    auto pv_accum = [&](int jglob) {
        #pragma unroll
        for (int jc = 0; jc < 4; ++jc) {
            __syncthreads();
            #pragma unroll
            for (int p = 0; p < 4; ++p) {
                int f4 = p * 256 + t;
                int j = f4 >> 4, dq = (f4 & 15) << 2;
                *(float4*)(sV + j * SVP + dq) =
                    *(const float4*)(vbase + (size_t)(jglob + jc * 64 + j) * DD + dq);
            }
            __syncthreads();
            #pragma unroll 4
            for (int j = 0; j < 64; j += 2) {
                float2 a[8];
                #pragma unroll
                for (int r = 0; r < 8; ++r)
                    a[r] = *(const float2*)(sP + (8 * w + r) * SKP + jc * 64 + j);
                ull b0 = *(const ull*)(sV + j * SVP + 2 * l);
                ull b1 = *(const ull*)(sV + (j + 1) * SVP + 2 * l);
                #pragma unroll
                for (int r = 0; r < 8; ++r) ffma2(oacc[r], pack2(a[r].x), b0);
                #pragma unroll
                for (int r = 0; r < 8; ++r) ffma2(oacc[r], pack2(a[r].y), b1);
            }
        }
    };

    // chunk 1 first (sP already holds normalized chunk-1 P)
    pv_accum(256);

    // chunk-0 fixup: re-read own raw values (L2), normalize, write attn + sP
    __syncthreads();  // PV reads of sP done before overwrite
    #pragma unroll
    for (int r = 0; r < 8; ++r) {
        int gi = qb + 8 * w + r;
        size_t arow = ((size_t)bh * L + gi) * L;
        float4 x0 = *(const float4*)(attn + arow + 4 * l);
        float4 x1 = *(const float4*)(attn + arow + 128 + 4 * l);
        float mM = M[r], iz = Zinv[r];
        float4 p0, p1;
        p0.x = __expf(x0.x - mM) * iz; p0.y = __expf(x0.y - mM) * iz;
        p0.z = __expf(x0.z - mM) * iz; p0.w = __expf(x0.w - mM) * iz;
        p1.x = __expf(x1.x - mM) * iz; p1.y = __expf(x1.y - mM) * iz;
        p1.z = __expf(x1.z - mM) * iz; p1.w = __expf(x1.w - mM) * iz;
        *(float4*)(attn + arow + 4 * l)       = p0;
        *(float4*)(attn + arow + 128 + 4 * l) = p1;
        *(float4*)(sP + (8 * w + r) * SKP + 4 * l)       = p0;
        *(float4*)(sP + (8 * w + r) * SKP + 128 + 4 * l) = p1;
    }

    // chunk 0 PV
    pv_accum(0);

    // write O: warp rows 8w..8w+7, lane d = 2l..2l+1
    #pragma unroll
    for (int r = 0; r < 8; ++r) {
        float2 ov = unpack2(oacc[r]);
        *(float2*)(out_o + ((size_t)bh * L + qb + 8 * w + r) * DD + 2 * l) = ov;
    }
}

// ---------------------------------------------------------------------------
extern "C" void kernel_launch(void* const* d_in, const int* in_sizes, int n_in,
                              void* d_out, int out_size) {
    const float* q     = (const float*)d_in[0];
    const float* k     = (const float*)d_in[1];
    const float* v     = (const float*)d_in[2];
    const float* omega = (const float*)d_in[3];
    const int*   mask  = (const int*)d_in[4];

    float* out_o    = (float*)d_out;
    float* out_attn = out_o + (size_t)NBH * L * DD;   // [output | attn]

    const int smem2 = (64 * SQP + 64 * SKP) * (int)sizeof(float);  // 83968
    cudaFuncSetAttribute(attn_fused, cudaFuncAttributeMaxDynamicSharedMemorySize, smem2);

    reduce_kv_kernel<<<dim3(8, NBH), 256>>>(k, v);
    attn_fused<<<dim3(8, NBH), 256, smem2>>>(q, omega, mask, out_attn, out_o);
}

// round 14
// speedup vs baseline: 1.0124x; 1.0124x over previous
#include <cuda_runtime.h>
#include <cstdint>

#define NBH 64
#define L   512
#define DD  64
#define SQP 68    // sQ / sV row pad (floats)
#define SKP 260   // sKT / sP row pad (floats)
#define SVP 68

typedef unsigned long long ull;

// Scratch (device globals; no allocation in kernel_launch)
__device__ float g_ksumT[NBH * DD * L];   // [bh][d][j]  (transposed)
__device__ float g_vsum [NBH * L * DD];   // [bh][j][d]  (natural)

__device__ __forceinline__ ull pack2(float x) {
    ull r; unsigned int xi = __float_as_uint(x);
    asm("mov.b64 %0, {%1, %1};" : "=l"(r) : "r"(xi));
    return r;
}
__device__ __forceinline__ ull pack2f(float x, float y) {
    ull r;
    asm("mov.b64 %0, {%1, %2};" : "=l"(r) : "f"(x), "f"(y));
    return r;
}
__device__ __forceinline__ void ffma2(ull& c, ull a, ull b) {
    asm("fma.rn.f32x2 %0, %1, %2, %0;" : "+l"(c) : "l"(a), "l"(b));
}
__device__ __forceinline__ float2 unpack2(ull x) {
    float2 f;
    asm("mov.b64 {%0, %1}, %2;" : "=f"(f.x), "=f"(f.y) : "l"(x));
    return f;
}

// ---------------------------------------------------------------------------
// K1: reduce r; ksum TRANSPOSED [bh][d][j] via smem transpose, vsum natural.
// ---------------------------------------------------------------------------
__global__ __launch_bounds__(256)
void reduce_kv_kernel(const float* __restrict__ k, const float* __restrict__ v) {
    __shared__ float sT[DD * 65];
    const int t  = threadIdx.x;
    const int jb = blockIdx.x;
    const int bh = blockIdx.y;

    #pragma unroll
    for (int p = 0; p < 4; ++p) {
        int f4 = p * 256 + t;
        int jl = f4 >> 4, dq = (f4 & 15) << 2;
        size_t base = (((size_t)bh * L + jb * 64 + jl) * 4) * DD + dq;
        float4 a0 = *(const float4*)(k + base);
        float4 a1 = *(const float4*)(k + base + DD);
        float4 a2 = *(const float4*)(k + base + 2 * DD);
        float4 a3 = *(const float4*)(k + base + 3 * DD);
        sT[(dq + 0) * 65 + jl] = (a0.x + a1.x) + (a2.x + a3.x);
        sT[(dq + 1) * 65 + jl] = (a0.y + a1.y) + (a2.y + a3.y);
        sT[(dq + 2) * 65 + jl] = (a0.z + a1.z) + (a2.z + a3.z);
        sT[(dq + 3) * 65 + jl] = (a0.w + a1.w) + (a2.w + a3.w);
        float4 b0 = *(const float4*)(v + base);
        float4 b1 = *(const float4*)(v + base + DD);
        float4 b2 = *(const float4*)(v + base + 2 * DD);
        float4 b3 = *(const float4*)(v + base + 3 * DD);
        float4 vs;
        vs.x = (b0.x + b1.x) + (b2.x + b3.x);
        vs.y = (b0.y + b1.y) + (b2.y + b3.y);
        vs.z = (b0.z + b1.z) + (b2.z + b3.z);
        vs.w = (b0.w + b1.w) + (b2.w + b3.w);
        *(float4*)(g_vsum + ((size_t)bh * L + jb * 64 + jl) * DD + dq) = vs;
    }
    __syncthreads();
    #pragma unroll
    for (int p = 0; p < 4; ++p) {
        int f4 = p * 256 + t;
        int dl = f4 >> 4, jq = (f4 & 15) << 2;
        float4 o;
        o.x = sT[dl * 65 + jq + 0];
        o.y = sT[dl * 65 + jq + 1];
        o.z = sT[dl * 65 + jq + 2];
        o.w = sT[dl * 65 + jq + 3];
        *(float4*)(g_ksumT + ((size_t)bh * DD + dl) * L + jb * 64 + jq) = o;
    }
}

// ---------------------------------------------------------------------------
// K2 (fused, no-max softmax): per CTA 64 q rows of one bh.
//   c=0: e=exp(s) -> raw store to attn; lane-partial Z
//   c=1: e kept in acc regs; single Z reduction; normalized P -> attn + sP
//   PV chunk1 (V tiles double-buffered); chunk0 fixup (L2 re-read, FMUL only);
//   PV chunk0; write O.
// smem: sQ[64][68] (aliased by sV) | sKT[64][260] (aliased by sP) = 84KB.
// ---------------------------------------------------------------------------
extern __shared__ float smem[];

__global__ __launch_bounds__(256, 2)
void attn_fused(const float* __restrict__ q,
                const float* __restrict__ omega,
                const int*   __restrict__ mask,
                float* __restrict__ attn,
                float* __restrict__ out_o) {
    float* sQ  = smem;              // [64][SQP]
    float* sKT = smem + 64 * SQP;   // [64][SKP]
    float* sV  = sQ;                // alias (sQ dead after QK mainloops)
    float* sP  = sKT;               // alias (sKT dead after c=1 mainloop)

    const int t  = threadIdx.x;
    const int bh = blockIdx.y;
    const int b  = bh >> 3;
    const int qb = blockIdx.x * 64;
    const int w  = t >> 5, l = t & 31;

    // fill sQ (fold 1/8)
    #pragma unroll
    for (int p = 0; p < 4; ++p) {
        int f4 = p * 256 + t;
        int r = f4 >> 4, dq = (f4 & 15) << 2;
        float4 qv = *(const float4*)(q + ((size_t)bh * L + qb + r) * DD + dq);
        qv.x *= 0.125f; qv.y *= 0.125f; qv.z *= 0.125f; qv.w *= 0.125f;
        *(float4*)(sQ + r * SQP + dq) = qv;
    }

    float Zp[8], Zinv[8];
    #pragma unroll
    for (int r = 0; r < 8; ++r) Zp[r] = 0.f;

    ull acc[8][4];

    #pragma unroll
    for (int c = 0; c < 2; ++c) {
        __syncthreads();
        // fill sKT chunk c
        #pragma unroll
        for (int p = 0; p < 16; ++p) {
            int f4 = p * 256 + t;
            int d = f4 >> 6, cq = (f4 & 63) << 2;
            *(float4*)(sKT + d * SKP + cq) =
                *(const float4*)(g_ksumT + ((size_t)bh * DD + d) * L + c * 256 + cq);
        }
        __syncthreads();

        #pragma unroll
        for (int r = 0; r < 8; ++r)
            #pragma unroll
            for (int i = 0; i < 4; ++i) acc[r][i] = 0;

        const float* bp = sKT + 4 * l;
        #pragma unroll 2
        for (int d = 0; d < DD; d += 2) {
            float2 a[8];
            #pragma unroll
            for (int r = 0; r < 8; ++r)
                a[r] = *(const float2*)(sQ + (8 * w + r) * SQP + d);
            #pragma unroll
            for (int dd = 0; dd < 2; ++dd) {
                ulonglong2 b0 = *(const ulonglong2*)(bp + (d + dd) * SKP);
                ulonglong2 b1 = *(const ulonglong2*)(bp + (d + dd) * SKP + 128);
                #pragma unroll
                for (int r = 0; r < 8; ++r) {
                    ull ar = pack2(dd ? a[r].y : a[r].x);
                    ffma2(acc[r][0], ar, b0.x);
                    ffma2(acc[r][1], ar, b0.y);
                    ffma2(acc[r][2], ar, b1.x);
                    ffma2(acc[r][3], ar, b1.y);
                }
            }
        }

        // epilogue: e = mask ? 0 : exp(u*omega); lane-partial Z
        #pragma unroll
        for (int r = 0; r < 8; ++r) {
            int gi = qb + 8 * w + r;
            size_t orow = ((size_t)b * L + gi) * L + c * 256;
            float4 o0 = *(const float4*)(omega + orow + 4 * l);
            float4 o1 = *(const float4*)(omega + orow + 128 + 4 * l);
            int4 m0 = *(const int4*)(mask + orow + 4 * l);
            int4 m1 = *(const int4*)(mask + orow + 128 + 4 * l);
            float2 u0 = unpack2(acc[r][0]), u1 = unpack2(acc[r][1]);
            float2 u2 = unpack2(acc[r][2]), u3 = unpack2(acc[r][3]);
            float e0 = m0.x ? 0.f : __expf(u0.x * o0.x);
            float e1 = m0.y ? 0.f : __expf(u0.y * o0.y);
            float e2 = m0.z ? 0.f : __expf(u1.x * o0.z);
            float e3 = m0.w ? 0.f : __expf(u1.y * o0.w);
            float e4 = m1.x ? 0.f : __expf(u2.x * o1.x);
            float e5 = m1.y ? 0.f : __expf(u2.y * o1.y);
            float e6 = m1.z ? 0.f : __expf(u3.x * o1.z);
            float e7 = m1.w ? 0.f : __expf(u3.y * o1.w);
            Zp[r] += ((e0 + e1) + (e2 + e3)) + ((e4 + e5) + (e6 + e7));
            if (c == 0) {
                size_t arow = ((size_t)bh * L + gi) * L;
                *(float4*)(attn + arow + 4 * l)       = make_float4(e0, e1, e2, e3);
                *(float4*)(attn + arow + 128 + 4 * l) = make_float4(e4, e5, e6, e7);
            } else {
                acc[r][0] = pack2f(e0, e1);
                acc[r][1] = pack2f(e2, e3);
                acc[r][2] = pack2f(e4, e5);
                acc[r][3] = pack2f(e6, e7);
            }
        }
    }

    // single Z reduction across lanes (covers both chunks)
    #pragma unroll
    for (int r = 0; r < 8; ++r) {
        float z = Zp[r];
        #pragma unroll
        for (int o = 16; o > 0; o >>= 1)
            z += __shfl_xor_sync(0xffffffffu, z, o);
        Zinv[r] = 1.0f / z;
    }

    __syncthreads();   // all QK mainloop reads of sKT done before sP writes

    // write normalized chunk-1 P to attn + sP
    #pragma unroll
    for (int r = 0; r < 8; ++r) {
        int gi = qb + 8 * w + r;
        float iz = Zinv[r];
        float2 e0 = unpack2(acc[r][0]), e1 = unpack2(acc[r][1]);
        float2 e2 = unpack2(acc[r][2]), e3 = unpack2(acc[r][3]);
        float4 p0 = make_float4(e0.x * iz, e0.y * iz, e1.x * iz, e1.y * iz);
        float4 p1 = make_float4(e2.x * iz, e2.y * iz, e3.x * iz, e3.y * iz);
        size_t arow = ((size_t)bh * L + gi) * L + 256;
        *(float4*)(attn + arow + 4 * l)       = p0;
        *(float4*)(attn + arow + 128 + 4 * l) = p1;
        *(float4*)(sP + (8 * w + r) * SKP + 4 * l)       = p0;
        *(float4*)(sP + (8 * w + r) * SKP + 128 + 4 * l) = p1;
    }

    // ------------------- PV accumulation -------------------
    const float* vbase = g_vsum + (size_t)bh * L * DD;
    ull oacc[8];
    #pragma unroll
    for (int r = 0; r < 8; ++r) oacc[r] = 0;

    // prefetch first V tile (tile 4 = chunk1 first)
    float4 vr[4];
    #pragma unroll
    for (int p = 0; p < 4; ++p) {
        int f4 = p * 256 + t;
        int j = f4 >> 4, dq = (f4 & 15) << 2;
        vr[p] = *(const float4*)(vbase + (size_t)(4 * 64 + j) * DD + dq);
    }

    #pragma unroll
    for (int idx = 0; idx < 8; ++idx) {
        const int tile = (idx + 4) & 7;     // 4,5,6,7, 0,1,2,3
        const int tloc = tile & 3;
        __syncthreads();                     // prior compute done reading sV / sP writes visible
        #pragma unroll
        for (int p = 0; p < 4; ++p) {
            int f4 = p * 256 + t;
            int j = f4 >> 4, dq = (f4 & 15) << 2;
            *(float4*)(sV + j * SVP + dq) = vr[p];
        }
        if (idx < 7) {
            const int nt = (idx + 5) & 7;
            #pragma unroll
            for (int p = 0; p < 4; ++p) {
                int f4 = p * 256 + t;
                int j = f4 >> 4, dq = (f4 & 15) << 2;
                vr[p] = *(const float4*)(vbase + (size_t)(nt * 64 + j) * DD + dq);
            }
        }
        __syncthreads();                     // sV ready

        #pragma unroll 4
        for (int j = 0; j < 64; j += 4) {
            float4 a4[8];
            #pragma unroll
            for (int r = 0; r < 8; ++r)
                a4[r] = *(const float4*)(sP + (8 * w + r) * SKP + tloc * 64 + j);
            ull b0 = *(const ull*)(sV + (j + 0) * SVP + 2 * l);
            ull b1 = *(const ull*)(sV + (j + 1) * SVP + 2 * l);
            ull b2 = *(const ull*)(sV + (j + 2) * SVP + 2 * l);
            ull b3 = *(const ull*)(sV + (j + 3) * SVP + 2 * l);
            #pragma unroll
            for (int r = 0; r < 8; ++r) ffma2(oacc[r], pack2(a4[r].x), b0);
            #pragma unroll
            for (int r = 0; r < 8; ++r) ffma2(oacc[r], pack2(a4[r].y), b1);
            #pragma unroll
            for (int r = 0; r < 8; ++r) ffma2(oacc[r], pack2(a4[r].z), b2);
            #pragma unroll
            for (int r = 0; r < 8; ++r) ffma2(oacc[r], pack2(a4[r].w), b3);
        }

        if (idx == 3) {
            // chunk-0 fixup: re-read raw e (L2-hot), scale by 1/Z, write attn + sP
            __syncwarp();  // lanes' sP reads (tile 7) done before overwriting rows
            #pragma unroll
            for (int r = 0; r < 8; ++r) {
                int gi = qb + 8 * w + r;
                size_t arow = ((size_t)bh * L + gi) * L;
                float4 x0 = *(const float4*)(attn + arow + 4 * l);
                float4 x1 = *(const float4*)(attn + arow + 128 + 4 * l);
                float iz = Zinv[r];
                x0.x *= iz; x0.y *= iz; x0.z *= iz; x0.w *= iz;
                x1.x *= iz; x1.y *= iz; x1.z *= iz; x1.w *= iz;
                *(float4*)(attn + arow + 4 * l)       = x0;
                *(float4*)(attn + arow + 128 + 4 * l) = x1;
                *(float4*)(sP + (8 * w + r) * SKP + 4 * l)       = x0;
                *(float4*)(sP + (8 * w + r) * SKP + 128 + 4 * l) = x1;
            }
        }
    }

    // write O: warp rows 8w..8w+7, lane d = 2l..2l+1
    #pragma unroll
    for (int r = 0; r < 8; ++r) {
        float2 ov = unpack2(oacc[r]);
        *(float2*)(out_o + ((size_t)bh * L + qb + 8 * w + r) * DD + 2 * l) = ov;
    }
}

// ---------------------------------------------------------------------------
extern "C" void kernel_launch(void* const* d_in, const int* in_sizes, int n_in,
                              void* d_out, int out_size) {
    const float* q     = (const float*)d_in[0];
    const float* k     = (const float*)d_in[1];
    const float* v     = (const float*)d_in[2];
    const float* omega = (const float*)d_in[3];
    const int*   mask  = (const int*)d_in[4];

    float* out_o    = (float*)d_out;
    float* out_attn = out_o + (size_t)NBH * L * DD;   // [output | attn]

    const int smem2 = (64 * SQP + 64 * SKP) * (int)sizeof(float);  // 83968
    cudaFuncSetAttribute(attn_fused, cudaFuncAttributeMaxDynamicSharedMemorySize, smem2);

    reduce_kv_kernel<<<dim3(8, NBH), 256>>>(k, v);
    attn_fused<<<dim3(8, NBH), 256, smem2>>>(q, omega, mask, out_attn, out_o);
}